// round 7
// baseline (speedup 1.0000x reference)
#include <cuda_runtime.h>
#include <math.h>
#include <stdint.h>

typedef unsigned long long ull;

#define XT_OFF    0
#define GRID_OFF  4194304
#define REG_OFF   7340032
#define MOVED_OFF 7340040

// scratch (__device__ globals: allowed)
__device__ __align__(16) float  g_xT[64*4*16384];   // [bw][c][i][j]
__device__ __align__(16) float  g_xb05[8*4*16384];  // [b][c][z][y]
__device__ __align__(16) float  g_distw[131072*8];  // [l][t]
__device__ __align__(16) float  g_h1[64*8*3721];    // [bw][oc][61][61]
__device__ __align__(16) float  g_h2[8*62720];      // [b][oc][28][28][8w]
__device__ float  g_fc1[256];
__device__ float  g_rt[64*12];                      // [(b*8+t)]: R row-major, then T
__device__ __align__(16) float2 g_wp1[4*49*8];      // [(i*49+p*7+q)*8+o] = {w,w}
__device__ __align__(16) float2 g_wp2[8*25*10];

__device__ __forceinline__ ull pk2(float lo, float hi){
  ull r; asm("mov.b64 %0,{%1,%2};" : "=l"(r) : "f"(lo), "f"(hi)); return r;
}
__device__ __forceinline__ void fma2(ull& d, ull a, ull b){
  asm("fma.rn.f32x2 %0,%1,%2,%0;" : "+l"(d) : "l"(a), "l"(b));
}
__device__ __forceinline__ float2 up2(ull v){
  float lo, hi; asm("mov.b64 {%0,%1},%2;" : "=f"(lo), "=f"(hi) : "l"(v));
  return make_float2(lo, hi);
}

// ---------------- pack weights ----------------
__global__ void k_pack(const float* __restrict__ c1w, const float* __restrict__ c2w){
  for (int idx = threadIdx.x; idx < 1568; idx += 512){
    int o = idx & 7, ipq = idx >> 3;
    float w = c1w[o*196 + ipq];            // ipq = i*49+p*7+q
    g_wp1[idx] = make_float2(w, w);
  }
  for (int idx = threadIdx.x; idx < 2000; idx += 512){
    int o = idx % 10, ipq = idx / 10;
    float w = c2w[o*200 + ipq];            // ipq = i*25+p*5+q
    g_wp2[idx] = make_float2(w, w);
  }
}

// ---------------- transpose x -> [bw][c][i][j] ----------------
__global__ void k_transpose(const float* __restrict__ x){
  __shared__ float s[128*9];
  int i  = blockIdx.x & 127;
  int bc = blockIdx.x >> 7;
  int b  = bc >> 2, c = bc & 3;
  int t  = threadIdx.x;
  const float* row = x + (size_t)blockIdx.x * 1024;
  #pragma unroll
  for (int e = 0; e < 8; e++) s[t*9 + e] = row[t*8 + e];
  __syncthreads();
  #pragma unroll
  for (int w = 0; w < 8; w++)
    g_xT[(((size_t)(b*8+w)*4 + c) << 14) + (i << 7) + t] = s[t*9 + w];
}

// ---------------- xb05 = 0.5*(x[...,3]+x[...,4]) ----------------
__global__ void k_xb05(const float* __restrict__ x){
  int idx = blockIdx.x*256 + threadIdx.x;   // [b][c][z][y], 524288
  if (idx < 524288)
    g_xb05[idx] = 0.5f*(x[(size_t)idx*8 + 3] + x[(size_t)idx*8 + 4]);
}

// ---------------- distw ----------------
__global__ void k_distw(){
  const float TX[8] = {32,32,96,96,32,96,64,64};
  const float TY[8] = {32,96,32,96,64,64,32,96};
  int l = blockIdx.x*256 + threadIdx.x;
  if (l >= 131072) return;
  float fi = (float)(l >> 10), fj = (float)((l >> 3) & 127), fk = (float)(l & 7);
  float w[8], s = 0.f;
  float dz2 = (fk - 4.f)*(fk - 4.f);
  #pragma unroll
  for (int t = 0; t < 8; t++){
    float dx = fi - TX[t], dy = fj - TY[t];
    float d = sqrtf(dx*dx + dy*dy + dz2);
    w[t] = expf(-d*0.1f); s += w[t];
  }
  float inv = 1.f/s;
  #pragma unroll
  for (int t = 0; t < 8; t++) g_distw[(size_t)l*8 + t] = w[t]*inv;
}

// ---------------- conv1 (f32x2) + pool + relu ----------------
// grid (2,4,64) block (16,16); dyn smem: 38*68 float4 (opt-in set host-side)
__global__ void __launch_bounds__(256) k_conv1(const float* __restrict__ c1b){
  extern __shared__ float4 sp4[];          // [38][68]
  __shared__ float2 wsm1[1568];
  int bw = blockIdx.z;
  int PR = 16*blockIdx.y, PC = 32*blockIdx.x;
  int tx = threadIdx.x, ty = threadIdx.y;
  int tid = ty*16 + tx;
  for (int i = tid; i < 1568; i += 256) wsm1[i] = g_wp1[i];
  const float* src = g_xT + (size_t)bw*4*16384;

  ull acc[8][2][2];
  #pragma unroll
  for (int o = 0; o < 8; o++){ acc[o][0][0]=0; acc[o][0][1]=0; acc[o][1][0]=0; acc[o][1][1]=0; }

  #pragma unroll 1
  for (int ic = 0; ic < 4; ic++){
    __syncthreads();
    for (int e = tid; e < 38*68; e += 256){
      int r = e/68, m = e - r*68;
      const float* rp = src + ic*16384 + (size_t)min(2*PR + r, 127)*128;
      int c0 = 2*PC + m;
      float4 v;
      v.x = rp[min(c0,127)];   v.y = rp[min(c0+1,127)];
      v.z = rp[min(c0+2,127)]; v.w = rp[min(c0+3,127)];
      sp4[e] = v;
    }
    __syncthreads();
    #pragma unroll 1
    for (int p = 0; p < 7; p++){
      int r0 = (2*ty + p)*68 + 4*tx;
      #pragma unroll
      for (int q = 0; q < 7; q++){
        float4 A0 = sp4[r0 + q];
        float4 A1 = sp4[r0 + 68 + q];
        ull a00 = pk2(A0.x, A0.y), a01 = pk2(A0.z, A0.w);
        ull a10 = pk2(A1.x, A1.y), a11 = pk2(A1.z, A1.w);
        const ull* wp = (const ull*)&wsm1[((ic*7 + p)*7 + q)*8];
        #pragma unroll
        for (int o = 0; o < 8; o++){
          ull w = wp[o];
          fma2(acc[o][0][0], a00, w); fma2(acc[o][0][1], a01, w);
          fma2(acc[o][1][0], a10, w); fma2(acc[o][1][1], a11, w);
        }
      }
    }
  }

  int pr = PR + ty, pc0 = PC + 2*tx;
  if (pr < 61){
    float* base = g_h1 + (size_t)bw*8*3721 + pr*61;
    #pragma unroll
    for (int o = 0; o < 8; o++){
      float bo = c1b[o];
      float2 r00 = up2(acc[o][0][0]), r10 = up2(acc[o][1][0]);
      float v0 = fmaxf(fmaxf(r00.x, r00.y), fmaxf(r10.x, r10.y)) + bo;
      if (pc0 < 61) base[o*3721 + pc0] = fmaxf(v0, 0.f);
      float2 r01 = up2(acc[o][0][1]), r11 = up2(acc[o][1][1]);
      float v1 = fmaxf(fmaxf(r01.x, r01.y), fmaxf(r11.x, r11.y)) + bo;
      if (pc0 + 1 < 61) base[o*3721 + pc0 + 1] = fmaxf(v1, 0.f);
    }
  }
}

// ---------------- conv2 (scalar) + pool + relu ----------------
// grid (64,2) block (28,14); dyn smem: 8*32*61 floats
__global__ void k_conv2(const float* __restrict__ c2b){
  extern __shared__ float s_in[];          // [8][32][61]
  __shared__ float ws2[2000];
  int bw = blockIdx.x, half = blockIdx.y;
  int tx = threadIdx.x, ty = threadIdx.y;
  int tid = ty*28 + tx;                    // 392 threads
  for (int i = tid; i < 2000; i += 392) ws2[i] = g_wp2[i].x;
  for (int e = tid; e < 8*32*61; e += 392){
    int ic = e/(32*61), rem = e - ic*32*61;
    int r = rem/61, c = rem - r*61;
    s_in[e] = g_h1[(size_t)bw*8*3721 + ic*3721 + (28*half + r)*61 + c];
  }
  __syncthreads();

  float acc[10][4];
  #pragma unroll
  for (int o = 0; o < 10; o++){ acc[o][0]=0; acc[o][1]=0; acc[o][2]=0; acc[o][3]=0; }

  #pragma unroll 1
  for (int ic = 0; ic < 8; ic++){
    #pragma unroll 1
    for (int p = 0; p < 5; p++){
      int rb = ic*32*61 + (2*ty + p)*61 + 2*tx;
      #pragma unroll
      for (int q = 0; q < 5; q++){
        float i00 = s_in[rb + q],      i01 = s_in[rb + q + 1];
        float i10 = s_in[rb + 61 + q], i11 = s_in[rb + 61 + q + 1];
        int wb = ((ic*5 + p)*5 + q)*10;
        #pragma unroll
        for (int o = 0; o < 10; o++){
          float w = ws2[wb + o];
          acc[o][0] += i00*w; acc[o][1] += i01*w;
          acc[o][2] += i10*w; acc[o][3] += i11*w;
        }
      }
    }
  }

  int b = bw >> 3, wsl = bw & 7;
  int dp = 14*half + ty, hp = tx;
  #pragma unroll
  for (int o = 0; o < 10; o++){
    float v = fmaxf(fmaxf(acc[o][0], acc[o][1]), fmaxf(acc[o][2], acc[o][3])) + c2b[o];
    g_h2[((size_t)(b*10 + o)*784 + dp*28 + hp)*8 + wsl] = fmaxf(v, 0.f);
  }
}

// ---------------- fc1 (float4 vectorized) ----------------
__global__ void k_fc1(const float* __restrict__ w1, const float* __restrict__ b1){
  __shared__ float sred[256];
  int bo = blockIdx.x, b = bo >> 5, o = bo & 31;
  const float4* f = (const float4*)(g_h2 + (size_t)b*62720);
  const float4* w = (const float4*)(w1 + (size_t)o*62720);
  float s = 0.f;
  for (int i = threadIdx.x; i < 15680; i += 256){
    float4 a = f[i], c = w[i];
    s += a.x*c.x + a.y*c.y + a.z*c.z + a.w*c.w;
  }
  sred[threadIdx.x] = s;
  __syncthreads();
  for (int st = 128; st > 0; st >>= 1){
    if (threadIdx.x < st) sred[threadIdx.x] += sred[threadIdx.x + st];
    __syncthreads();
  }
  if (threadIdx.x == 0) g_fc1[bo] = sred[0] + b1[o];
}

// ---------------- fc2 + tanh + rigid transforms ----------------
__global__ void k_fc2(const float* __restrict__ w2, const float* __restrict__ b2){
  int tid = threadIdx.x;
  if (tid >= 64) return;
  int b = tid >> 3, t = tid & 7;
  float th[6];
  #pragma unroll
  for (int j = 0; j < 6; j++){
    int o = t*6 + j;
    float s = b2[o];
    #pragma unroll
    for (int m = 0; m < 32; m++) s += fmaxf(g_fc1[b*32 + m], 0.f)*w2[o*32 + m];
    th[j] = tanhf(s);
  }
  const float PI = 3.14159274101257324f;
  float a0 = PI*th[0], a1 = PI*th[1], a2 = PI*th[2];
  float c0 = cosf(a0), s0 = sinf(a0);
  float c1 = cosf(a1), s1 = sinf(a1);
  float c2 = cosf(a2), s2 = sinf(a2);
  float R[9];
  R[0] = c0*c1;  R[1] = -s0*c2 + c0*s1*s2;  R[2] = s0*s2 + c0*s1*c2;
  R[3] = s0*c1;  R[4] =  c0*c2 + s0*s1*s2;  R[5] = -c0*s2 + s0*s1*c2;
  R[6] = -s1;    R[7] =  c1*s2;             R[8] = c1*c2;
  float* rt = g_rt + tid*12;
  #pragma unroll
  for (int e = 0; e < 9; e++) rt[e] = R[e];
  const float szv[3] = {128.f, 128.f, 8.f};
  const float cen[3] = {64.f, 64.f, 4.f};
  #pragma unroll
  for (int s = 0; s < 3; s++)
    rt[9 + s] = th[3 + s]*szv[s] + cen[s] - (64.f*R[s] + 64.f*R[3 + s] + 4.f*R[6 + s]);
}

// ---------------- flow + grid + sample ----------------
// grid (64,8) block 256; thread = one (i,j), loops k 0..7
__global__ void __launch_bounds__(256) k_flow(float* __restrict__ out){
  __shared__ float srt[96];
  int b = blockIdx.y;
  int ij = blockIdx.x*256 + threadIdx.x;
  if (threadIdx.x < 96) srt[threadIdx.x] = g_rt[b*96 + threadIdx.x];
  __syncthreads();
  float fi = (float)(ij >> 7), fj = (float)(ij & 127);

  float v[8][2], dR[8][2];
  #pragma unroll
  for (int t = 0; t < 8; t++){
    const float* m = srt + t*12;
    v[t][0] = fi*m[0] + fj*m[3] + m[9];
    v[t][1] = fi*m[1] + fj*m[4] + m[10];
    dR[t][0] = m[6]; dR[t][1] = m[7];
  }
  const float* tb0 = g_xb05 + ((size_t)(b*4 + 0) << 14);
  const float* tb1 = g_xb05 + ((size_t)(b*4 + 1) << 14);
  const float* tb2 = g_xb05 + ((size_t)(b*4 + 2) << 14);
  const float* tb3 = g_xb05 + ((size_t)(b*4 + 3) << 14);

  float x0[8], x1[8], x2[8], x3[8], nf0b[8], nf1b[8];
  #pragma unroll
  for (int k = 0; k < 8; k++){
    const float4* W = (const float4*)(g_distw + ((size_t)ij*8 + k)*8);
    float4 wA = W[0], wB = W[1];
    float F0 = wA.x*v[0][0] + wA.y*v[1][0] + wA.z*v[2][0] + wA.w*v[3][0]
             + wB.x*v[4][0] + wB.y*v[5][0] + wB.z*v[6][0] + wB.w*v[7][0];
    float F1 = wA.x*v[0][1] + wA.y*v[1][1] + wA.z*v[2][1] + wA.w*v[3][1]
             + wB.x*v[4][1] + wB.y*v[5][1] + wB.z*v[6][1] + wB.w*v[7][1];
    nf0b[k] = F0*0.015625f - 1.f;
    nf1b[k] = F1*0.015625f - 1.f;
    float iz = F0 - 0.5f, iy = F1 - 0.5f;
    float z0f = floorf(iz), y0f = floorf(iy);
    float fz = iz - z0f, fy = iy - y0f;
    int z0 = (int)z0f, y0 = (int)y0f;
    float wz0 = (z0 >= 0 && z0 < 128)     ? (1.f - fz) : 0.f;
    float wz1 = (z0 >= -1 && z0 < 127)    ? fz         : 0.f;
    float wy0 = (y0 >= 0 && y0 < 128)     ? (1.f - fy) : 0.f;
    float wy1 = (y0 >= -1 && y0 < 127)    ? fy         : 0.f;
    int z0c = min(max(z0, 0), 127), z1c = min(max(z0 + 1, 0), 127);
    int y0c = min(max(y0, 0), 127), y1c = min(max(y0 + 1, 0), 127);
    float w00 = wz0*wy0, w01 = wz0*wy1, w10 = wz1*wy0, w11 = wz1*wy1;
    int o00 = z0c*128 + y0c, o01 = z0c*128 + y1c;
    int o10 = z1c*128 + y0c, o11 = z1c*128 + y1c;
    x0[k] = w00*tb0[o00] + w01*tb0[o01] + w10*tb0[o10] + w11*tb0[o11];
    x1[k] = w00*tb1[o00] + w01*tb1[o01] + w10*tb1[o10] + w11*tb1[o11];
    x2[k] = w00*tb2[o00] + w01*tb2[o01] + w10*tb2[o10] + w11*tb2[o11];
    x3[k] = w00*tb3[o00] + w01*tb3[o01] + w10*tb3[o10] + w11*tb3[o11];
    #pragma unroll
    for (int t = 0; t < 8; t++){ v[t][0] += dR[t][0]; v[t][1] += dR[t][1]; }
  }

  float4* go = (float4*)(out + GRID_OFF + ((size_t)b*131072 + (size_t)ij*8)*3);
  go[0] = make_float4(0.f, nf1b[0], nf0b[0], 0.f);
  go[1] = make_float4(nf1b[1], nf0b[1], 0.f, nf1b[2]);
  go[2] = make_float4(nf0b[2], 0.f, nf1b[3], nf0b[3]);
  go[3] = make_float4(0.f, nf1b[4], nf0b[4], 0.f);
  go[4] = make_float4(nf1b[5], nf0b[5], 0.f, nf1b[6]);
  go[5] = make_float4(nf0b[6], 0.f, nf1b[7], nf0b[7]);

  float4* xo0 = (float4*)(out + XT_OFF + (((size_t)(b*4 + 0)) << 17) + (size_t)ij*8);
  float4* xo1 = (float4*)(out + XT_OFF + (((size_t)(b*4 + 1)) << 17) + (size_t)ij*8);
  float4* xo2 = (float4*)(out + XT_OFF + (((size_t)(b*4 + 2)) << 17) + (size_t)ij*8);
  float4* xo3 = (float4*)(out + XT_OFF + (((size_t)(b*4 + 3)) << 17) + (size_t)ij*8);
  xo0[0] = make_float4(x0[0], x0[1], x0[2], x0[3]); xo0[1] = make_float4(x0[4], x0[5], x0[6], x0[7]);
  xo1[0] = make_float4(x1[0], x1[1], x1[2], x1[3]); xo1[1] = make_float4(x1[4], x1[5], x1[6], x1[7]);
  xo2[0] = make_float4(x2[0], x2[1], x2[2], x2[3]); xo2[1] = make_float4(x2[4], x2[5], x2[6], x2[7]);
  xo3[0] = make_float4(x3[0], x3[1], x3[2], x3[3]); xo3[1] = make_float4(x3[4], x3[5], x3[6], x3[7]);
}

// ---------------- moved + reg ----------------
__global__ void k_moved(const float* __restrict__ pos, const float* __restrict__ centers,
                        float* __restrict__ out){
  __shared__ float red[128];
  int b = blockIdx.x, n = threadIdx.x;
  float nv = 0.f;
  if (n < 100){
    float p0 = pos[(b*100 + n)*3 + 0];
    float p1 = pos[(b*100 + n)*3 + 1];
    float p2 = pos[(b*100 + n)*3 + 2];
    int i0 = (int)fminf(fmaxf(rintf(p0), 0.f), 127.f);
    int i1 = (int)fminf(fmaxf(rintf(p1), 0.f), 127.f);
    int i2 = (int)fminf(fmaxf(rintf(p2), 0.f), 7.f);
    size_t l = (size_t)(i0*128 + i1)*8 + i2;
    const float* g = out + GRID_OFF + ((size_t)b*131072 + l)*3;
    float nf1 = g[1], nf0 = g[2];
    float m0 = 2.f*p0 - (0.5f + 0.5f*nf0)*127.f;
    float m1 = 2.f*p1 - (0.5f + 0.5f*nf1)*127.f;
    float m2 = 2.f*p2 - 3.5f;
    out[MOVED_OFF + (b*100 + n)*3 + 0] = m0;
    out[MOVED_OFF + (b*100 + n)*3 + 1] = m1;
    out[MOVED_OFF + (b*100 + n)*3 + 2] = m2;
    float d0 = m0 - centers[n*3 + 0];
    float d1 = m1 - centers[n*3 + 1];
    float d2 = m2 - centers[n*3 + 2];
    nv = sqrtf(d0*d0 + d1*d1 + d2*d2);
  }
  red[n] = nv;
  __syncthreads();
  for (int s = 64; s > 0; s >>= 1){
    if (n < s) red[n] += red[n + s];
    __syncthreads();
  }
  if (n == 0) out[REG_OFF + b] = red[0]*0.01f;
}

extern "C" void kernel_launch(void* const* d_in, const int* in_sizes, int n_in,
                              void* d_out, int out_size){
  const float* x    = (const float*)d_in[0];
  const float* pos  = (const float*)d_in[1];
  const float* cen  = (const float*)d_in[2];
  const float* c1w  = (const float*)d_in[3];
  const float* c1b  = (const float*)d_in[4];
  const float* c2w  = (const float*)d_in[5];
  const float* c2b  = (const float*)d_in[6];
  const float* fc1w = (const float*)d_in[7];
  const float* fc1b = (const float*)d_in[8];
  const float* fc2w = (const float*)d_in[9];
  const float* fc2b = (const float*)d_in[10];
  float* out = (float*)d_out;

  // opt-in smem limits (dynamic alone and dynamic+static both exceed 48KB defaults)
  cudaFuncSetAttribute(k_conv1, cudaFuncAttributeMaxDynamicSharedMemorySize, 38*68*16);
  cudaFuncSetAttribute(k_conv2, cudaFuncAttributeMaxDynamicSharedMemorySize, 8*32*61*4);

  k_pack<<<1, 512>>>(c1w, c2w);
  k_transpose<<<4096, 128>>>(x);
  k_xb05<<<2048, 256>>>(x);
  k_distw<<<512, 256>>>();
  k_conv1<<<dim3(2,4,64), dim3(16,16), 38*68*16>>>(c1b);
  k_conv2<<<dim3(64,2), dim3(28,14), 8*32*61*4>>>(c2b);
  k_fc1<<<256, 256>>>(fc1w, fc1b);
  k_fc2<<<1, 64>>>(fc2w, fc2b);
  k_flow<<<dim3(64,8), 256>>>(out);
  k_moved<<<8, 128>>>(pos, cen, out);
}